// round 16
// baseline (speedup 1.0000x reference)
#include <cuda_runtime.h>
#include <math.h>

#define NB 32
#define NT 2048
#define CF 128
#define NQ 256
#define HA 192
#define GA 576
#define HB 32
#define GB 96
#define JC 48

typedef unsigned long long ull;

__device__ float  g_embA[3 * NQ * GA];
__device__ float  g_gia[NB * NT * GA];
__device__ float  g_ha [NB * NT * HA];
__device__ float  g_gib[NB * NT * GB];
__device__ float  g_hb [NB * NT * HB];

__device__ __forceinline__ float sigf(float x) { return 1.f / (1.f + __expf(-x)); }
__device__ __forceinline__ float tanh_fast(float x) {
    float t = __expf(-2.f * fabsf(x));
    return copysignf(__fdividef(1.f - t, 1.f + t), x);
}
__device__ __forceinline__ float tanh_poly(float x) {
    float t = __expf(-2.f * fabsf(x));
    float u = 1.f + t;
    float d = fmaf(-0.5f, t, 1.f);
    d = d * fmaf(-u, d, 2.f);
    d = d * fmaf(-u, d, 2.f);
    d = d * fmaf(-u, d, 2.f);
    return copysignf((1.f - t) * d, x);
}
__device__ __forceinline__ ull fma2(ull a, ull b, ull c) {
    ull d;
    asm("fma.rn.f32x2 %0, %1, %2, %3;" : "=l"(d) : "l"(a), "l"(b), "l"(c));
    return d;
}
__device__ __forceinline__ float sum2(ull a) {
    float lo, hi;
    asm("mov.b64 {%0,%1}, %2;" : "=f"(lo), "=f"(hi) : "l"(a));
    return lo + hi;
}
__device__ __forceinline__ ull splat2(float x) {
    ull d;
    asm("mov.b64 %0, {%1, %1};" : "=l"(d) : "f"(x));
    return d;
}
__device__ __forceinline__ float2 unpk2(ull a) {
    float lo, hi;
    asm("mov.b64 {%0,%1}, %2;" : "=f"(lo), "=f"(hi) : "l"(a));
    return make_float2(lo, hi);
}
__device__ __forceinline__ unsigned smem_u32(const void* p) {
    unsigned a;
    asm("{ .reg .u64 t; cvta.to.shared.u64 t, %1; cvt.u32.u64 %0, t; }" : "=r"(a) : "l"(p));
    return a;
}
__device__ __forceinline__ unsigned mapa_u32(unsigned a, unsigned rank) {
    unsigned r;
    asm("mapa.shared::cluster.u32 %0, %1, %2;" : "=r"(r) : "r"(a), "r"(rank));
    return r;
}

// K-nop: keeps k_scanA in the ncu-captured 4th-launch slot.
__global__ void k_nop() {}

// K1: embA[s][q][o] = sum_d emb[q][d] * w_ih_a[o][128 + s*256 + d]
__global__ void k_proj(const float* __restrict__ emb, const float* __restrict__ wiha) {
    __shared__ float es[32][65];
    __shared__ float ws[64][65];
    int s = blockIdx.z, q0 = blockIdx.y * 32, o0 = blockIdx.x * 64;
    int t = threadIdx.x, tx = t % 64, ty = t / 64;
    float acc[8];
#pragma unroll
    for (int m = 0; m < 8; m++) acc[m] = 0.f;
    for (int kc = 0; kc < 4; kc++) {
        int k0 = kc * 64;
        for (int i = t; i < 32 * 64; i += 256) {
            int r = i >> 6, c = i & 63;
            es[r][c] = emb[(q0 + r) * NQ + k0 + c];
        }
        for (int i = t; i < 64 * 64; i += 256) {
            int r = i >> 6, c = i & 63;
            ws[r][c] = wiha[(o0 + r) * 896 + 128 + s * 256 + k0 + c];
        }
        __syncthreads();
#pragma unroll 8
        for (int k = 0; k < 64; k++) {
            float wv = ws[tx][k];
#pragma unroll
            for (int m = 0; m < 8; m++) acc[m] = fmaf(es[ty + 4 * m][k], wv, acc[m]);
        }
        __syncthreads();
    }
#pragma unroll
    for (int m = 0; m < 8; m++)
        g_embA[(s * NQ + q0 + ty + 4 * m) * GA + o0 + tx] = acc[m];
}

// K2: gia = f @ Wf^T + lerp(embA). k-major conflict-free tiles + FFMA2 compute.
__global__ void k_gia(const float* __restrict__ f, const float* __restrict__ p,
                      const float* __restrict__ sp, const float* __restrict__ ep,
                      const float* __restrict__ wiha) {
    __shared__ float fsk[64][68];
    __shared__ float wsk[64][68];
    __shared__ int   slo[3][64];
    __shared__ float sfr[3][64];
    int o0 = blockIdx.x * 64, bt0 = blockIdx.y * 64;
    int t = threadIdx.x, tx = t & 15, ty = t >> 4;
    if (t < 192) {
        int c = t >> 6, r = t & 63;
        const float* src = (c == 0) ? p : ((c == 1) ? sp : ep);
        float raw = src[bt0 + r] * 255.f;
        int lo = (int)floorf(raw);
        lo = max(0, min(lo, 254));
        slo[c][r] = lo;
        sfr[c][r] = raw - (float)lo;
    }
    ull acc2[4][2];
#pragma unroll
    for (int i = 0; i < 4; i++) { acc2[i][0] = 0ull; acc2[i][1] = 0ull; }
    for (int kc = 0; kc < 2; kc++) {
        int k0 = kc * 64;
        for (int i = t; i < 64 * 64; i += 256) {
            int r = i >> 6, c = i & 63;
            fsk[c][r] = f[(bt0 + r) * CF + k0 + c];
        }
        for (int i = t; i < 64 * 64; i += 256) {
            int r = i >> 6, c = i & 63;
            wsk[c][r] = wiha[(o0 + r) * 896 + k0 + c];
        }
        __syncthreads();
#pragma unroll 4
        for (int k = 0; k < 64; k++) {
            ulonglong2 wv2 = *(const ulonglong2*)&wsk[k][4 * tx];
            float4 fv = *(const float4*)&fsk[k][4 * ty];
            ull f0 = splat2(fv.x), f1 = splat2(fv.y), f2 = splat2(fv.z), f3 = splat2(fv.w);
            acc2[0][0] = fma2(f0, wv2.x, acc2[0][0]);
            acc2[0][1] = fma2(f0, wv2.y, acc2[0][1]);
            acc2[1][0] = fma2(f1, wv2.x, acc2[1][0]);
            acc2[1][1] = fma2(f1, wv2.y, acc2[1][1]);
            acc2[2][0] = fma2(f2, wv2.x, acc2[2][0]);
            acc2[2][1] = fma2(f2, wv2.y, acc2[2][1]);
            acc2[3][0] = fma2(f3, wv2.x, acc2[3][0]);
            acc2[3][1] = fma2(f3, wv2.y, acc2[3][1]);
        }
        __syncthreads();
    }
#pragma unroll
    for (int i = 0; i < 4; i++) {
        int r = 4 * ty + i;
        float2 p01 = unpk2(acc2[i][0]);
        float2 p23 = unpk2(acc2[i][1]);
        float a0v = p01.x, a1v = p01.y, a2v = p23.x, a3v = p23.y;
#pragma unroll
        for (int c = 0; c < 3; c++) {
            int   lo = slo[c][r];
            float fr = sfr[c][r];
            const float4 v0 = *(const float4*)&g_embA[(c * NQ + lo) * GA + o0 + 4 * tx];
            const float4 v1 = *(const float4*)&g_embA[(c * NQ + lo + 1) * GA + o0 + 4 * tx];
            a0v += v0.x + fr * (v1.x - v0.x);
            a1v += v0.y + fr * (v1.y - v0.y);
            a2v += v0.z + fr * (v1.z - v0.z);
            a3v += v0.w + fr * (v1.w - v0.w);
        }
        *(float4*)&g_gia[(bt0 + r) * GA + o0 + 4 * tx] = make_float4(a0v, a1v, a2v, a3v);
    }
}

// K3: GRU-A scan — TWO batches per 4-CTA cluster. R12's owner-directed
// exchange (432 remote stores/batch) + R8's barrier amortization (one
// barrier.cluster per 2 batch-steps). Weights shared between batches;
// gates in disjoint warps (batch0: tid<192 owners, batch1: tid in [192,384)).
__global__ void __cluster_dims__(4, 1, 1) __launch_bounds__(GA, 1)
k_scanA(const float* __restrict__ whha) {
    __shared__ __align__(16) float hbuf[2][2][JC];   // [buf][batch][slice]
    __shared__ float part[2][2][4][GA];              // [buf][batch][src_rank][o]

    int o = threadIdx.x;
    int cid = blockIdx.x >> 2;                       // cluster 0..15
    unsigned rank;
    asm("mov.u32 %0, %%cluster_ctarank;" : "=r"(rank));

    ull w2[24];
    {
        const ulonglong2* wp = (const ulonglong2*)(whha + o * HA + rank * JC);
#pragma unroll
        for (int k = 0; k < 12; k++) {
            ulonglong2 v = wp[k];
            w2[2 * k] = v.x;
            w2[2 * k + 1] = v.y;
        }
    }

    if (o < JC) { hbuf[0][0][o] = 0.f; hbuf[0][1][o] = 0.f; }
    __syncthreads();

    int owner = (o % HA) / JC;
    bool local_dst = (owner == (int)rank);
    unsigned pa[2][2];
#pragma unroll
    for (int b = 0; b < 2; b++)
#pragma unroll
        for (int bb = 0; bb < 2; bb++)
            pa[b][bb] = mapa_u32(smem_u32(&part[b][bb][rank][o]), (unsigned)owner);

    // gate roles: batch0 gates in tid [rank*48, rank*48+48); batch1 in 192+same
    bool gateA = (o < HA) && (o / JC == (int)rank);
    int  o2 = o - HA;
    bool gateB = (o >= HA) && (o < 2 * HA) && (o2 / JC == (int)rank);
    bool gate = gateA || gateB;
    int  hi = gateA ? o : o2;                        // owned h index
    int  bb_own = gateA ? 0 : 1;
    int  batch = cid * 2 + bb_own;
    const float* giaG = g_gia + (size_t)batch * NT * GA;
    float h_old = 0.f;
    float gr_i = 0.f, gz_i = 0.f, gn_i = 0.f;
    if (gate) {
        gr_i = giaG[hi]; gz_i = giaG[HA + hi]; gn_i = giaG[2 * HA + hi];
    }

    for (int t = 0; t < NT; t++) {
        int b = t & 1;
        float ngr = 0.f, ngz = 0.f, ngn = 0.f;
        if (gate && t + 1 < NT) {
            const float* g2 = giaG + (size_t)(t + 1) * GA;
            ngr = g2[hi]; ngz = g2[HA + hi]; ngn = g2[2 * HA + hi];
        }
        // FMA partials for batch 0
        {
            ull a0 = 0ull, a1 = 0ull, a2 = 0ull, a3 = 0ull;
            const ulonglong2* h2 = (const ulonglong2*)hbuf[b][0];
#pragma unroll
            for (int k = 0; k < 6; k++) {
                ulonglong2 hv0 = h2[2 * k];
                ulonglong2 hv1 = h2[2 * k + 1];
                a0 = fma2(w2[4 * k + 0], hv0.x, a0);
                a1 = fma2(w2[4 * k + 1], hv0.y, a1);
                a2 = fma2(w2[4 * k + 2], hv1.x, a2);
                a3 = fma2(w2[4 * k + 3], hv1.y, a3);
            }
            float ps = (sum2(a0) + sum2(a1)) + (sum2(a2) + sum2(a3));
            if (local_dst)
                part[b][0][rank][o] = ps;
            else
                asm volatile("st.shared::cluster.f32 [%0], %1;" :: "r"(pa[b][0]), "f"(ps));
        }
        // FMA partials for batch 1
        {
            ull a0 = 0ull, a1 = 0ull, a2 = 0ull, a3 = 0ull;
            const ulonglong2* h2 = (const ulonglong2*)hbuf[b][1];
#pragma unroll
            for (int k = 0; k < 6; k++) {
                ulonglong2 hv0 = h2[2 * k];
                ulonglong2 hv1 = h2[2 * k + 1];
                a0 = fma2(w2[4 * k + 0], hv0.x, a0);
                a1 = fma2(w2[4 * k + 1], hv0.y, a1);
                a2 = fma2(w2[4 * k + 2], hv1.x, a2);
                a3 = fma2(w2[4 * k + 3], hv1.y, a3);
            }
            float ps = (sum2(a0) + sum2(a1)) + (sum2(a2) + sum2(a3));
            if (local_dst)
                part[b][1][rank][o] = ps;
            else
                asm volatile("st.shared::cluster.f32 [%0], %1;" :: "r"(pa[b][1]), "f"(ps));
        }

        asm volatile("barrier.cluster.arrive.aligned;" ::: "memory");
        asm volatile("barrier.cluster.wait.aligned;" ::: "memory");

        if (gate) {
            float rr = gr_i, zz = gz_i, np = 0.f;
            const float* pb = &part[b][bb_own][0][0];
#pragma unroll
            for (int k = 0; k < 4; k++) {
                rr += pb[k * GA + hi];
                zz += pb[k * GA + HA + hi];
                np += pb[k * GA + 2 * HA + hi];
            }
            float rg = sigf(rr);
            float zg = sigf(zz);
            float n  = tanh_fast(gn_i + rg * np);
            float hn = (1.f - zg) * n + zg * h_old;
            h_old = hn;
            hbuf[b ^ 1][bb_own][hi - (int)rank * JC] = hn;
            g_ha[(size_t)(batch * NT + t) * HA + hi] = hn;
        }
        __syncthreads();
        gr_i = ngr; gz_i = ngz; gn_i = ngn;
    }
}

// K4: gib = concat(h_a, f) @ w_ih_b^T. k-major tiles + FFMA2 compute.
__global__ void __launch_bounds__(384) k_gib(const float* __restrict__ f,
                                             const float* __restrict__ wihb) {
    __shared__ float xsk[64][68];
    __shared__ float wskb[64][100];
    int bt0 = blockIdx.x * 64;
    int t = threadIdx.x, tx = t % 24, ty = t / 24;
    ull acc2[4][2];
#pragma unroll
    for (int i = 0; i < 4; i++) { acc2[i][0] = 0ull; acc2[i][1] = 0ull; }
    for (int kc = 0; kc < 5; kc++) {
        int k0 = kc * 64;
        for (int i = t; i < 64 * 64; i += 384) {
            int r = i >> 6, c = i & 63;
            xsk[c][r] = (k0 < HA) ? g_ha[(bt0 + r) * HA + k0 + c]
                                  : f[(bt0 + r) * CF + (k0 - HA) + c];
        }
        for (int i = t; i < 96 * 64; i += 384) {
            int r = i >> 6, c = i & 63;
            wskb[c][r] = wihb[r * 320 + k0 + c];
        }
        __syncthreads();
#pragma unroll 4
        for (int k = 0; k < 64; k++) {
            ulonglong2 wv2 = *(const ulonglong2*)&wskb[k][4 * tx];
            float4 xv = *(const float4*)&xsk[k][4 * ty];
            ull x0 = splat2(xv.x), x1 = splat2(xv.y), x2 = splat2(xv.z), x3 = splat2(xv.w);
            acc2[0][0] = fma2(x0, wv2.x, acc2[0][0]);
            acc2[0][1] = fma2(x0, wv2.y, acc2[0][1]);
            acc2[1][0] = fma2(x1, wv2.x, acc2[1][0]);
            acc2[1][1] = fma2(x1, wv2.y, acc2[1][1]);
            acc2[2][0] = fma2(x2, wv2.x, acc2[2][0]);
            acc2[2][1] = fma2(x2, wv2.y, acc2[2][1]);
            acc2[3][0] = fma2(x3, wv2.x, acc2[3][0]);
            acc2[3][1] = fma2(x3, wv2.y, acc2[3][1]);
        }
        __syncthreads();
    }
#pragma unroll
    for (int i = 0; i < 4; i++) {
        float2 p01 = unpk2(acc2[i][0]);
        float2 p23 = unpk2(acc2[i][1]);
        *(float4*)&g_gib[(bt0 + 4 * ty + i) * GB + 4 * tx] =
            make_float4(p01.x, p01.y, p23.x, p23.y);
    }
}

// K5: GRU-B scan — 4 batches/CTA, one warp per batch, h in smem, FFMA2
__global__ void __launch_bounds__(128) k_scanB(const float* __restrict__ whhb) {
    __shared__ __align__(16) float hsm[4][HB];
    int l = threadIdx.x & 31, wi = threadIdx.x >> 5;
    int b = blockIdx.x * 4 + wi;
    ull wr2[16], wz2[16], wn2[16];
    {
        const ulonglong2* pr = (const ulonglong2*)(whhb + l * HB);
        const ulonglong2* pz = (const ulonglong2*)(whhb + (HB + l) * HB);
        const ulonglong2* pn = (const ulonglong2*)(whhb + (2 * HB + l) * HB);
#pragma unroll
        for (int k = 0; k < 8; k++) {
            ulonglong2 vr = pr[k], vz = pz[k], vn = pn[k];
            wr2[2 * k] = vr.x; wr2[2 * k + 1] = vr.y;
            wz2[2 * k] = vz.x; wz2[2 * k + 1] = vz.y;
            wn2[2 * k] = vn.x; wn2[2 * k + 1] = vn.y;
        }
    }
    float h = 0.f;
    hsm[wi][l] = 0.f;
    __syncwarp();
    int bT = b * NT;
    const float* gi0 = &g_gib[(size_t)bT * GB];
    float gi_r = gi0[l], gi_z = gi0[HB + l], gi_n = gi0[2 * HB + l];
    for (int t = 0; t < NT; t++) {
        float nr = 0.f, nz = 0.f, nn = 0.f;
        if (t + 1 < NT) {
            const float* g2 = &g_gib[(size_t)(bT + t + 1) * GB];
            nr = g2[l]; nz = g2[HB + l]; nn = g2[2 * HB + l];
        }
        ull ar = 0ull, az = 0ull, an = 0ull;
        const ulonglong2* h2 = (const ulonglong2*)hsm[wi];
#pragma unroll
        for (int k = 0; k < 8; k++) {
            ulonglong2 hv = h2[k];
            ar = fma2(wr2[2 * k], hv.x, ar);
            az = fma2(wz2[2 * k], hv.x, az);
            an = fma2(wn2[2 * k], hv.x, an);
            ar = fma2(wr2[2 * k + 1], hv.y, ar);
            az = fma2(wz2[2 * k + 1], hv.y, az);
            an = fma2(wn2[2 * k + 1], hv.y, an);
        }
        float r = sigf(gi_r + sum2(ar));
        float z = sigf(gi_z + sum2(az));
        float n = tanh_fast(gi_n + r * sum2(an));
        h = (1.f - z) * n + z * h;
        __syncwarp();
        hsm[wi][l] = h;
        g_hb[(size_t)(bT + t) * HB + l] = h;
        __syncwarp();
        gi_r = nr; gi_z = nz; gi_n = nn;
    }
}

// K6: out[bt][q] = tanh(fc)*a summed over pair — FFMA2 dot products.
__global__ void __launch_bounds__(256) k_fc(const float* __restrict__ fcw,
                                            const float* __restrict__ fcb,
                                            const float* __restrict__ a,
                                            float* __restrict__ out) {
    __shared__ __align__(8) float hs[32][34];
    int q = threadIdx.x;
    int bt0 = blockIdx.x * 32;
    for (int i = q; i < 32 * 32; i += 256) {
        int r = i >> 5, c = i & 31;
        hs[r][c] = g_hb[(bt0 + r) * HB + c];
    }
    __syncthreads();
    ull w02[16], w12[16];
    {
        const ulonglong2* p0 = (const ulonglong2*)(fcw + (2 * q) * HB);
        const ulonglong2* p1 = (const ulonglong2*)(fcw + (2 * q + 1) * HB);
#pragma unroll
        for (int k = 0; k < 8; k++) {
            ulonglong2 v0 = p0[k], v1 = p1[k];
            w02[2 * k] = v0.x; w02[2 * k + 1] = v0.y;
            w12[2 * k] = v1.x; w12[2 * k + 1] = v1.y;
        }
    }
    float b0 = fcb[2 * q], b1 = fcb[2 * q + 1];
    float a0 = a[2 * q],   a1 = a[2 * q + 1];
    for (int r = 0; r < 32; r++) {
        ull s02 = 0ull, s12 = 0ull;
        const ull* hv2 = (const ull*)hs[r];
#pragma unroll
        for (int k = 0; k < 16; k++) {
            ull hv = hv2[k];
            s02 = fma2(w02[k], hv, s02);
            s12 = fma2(w12[k], hv, s12);
        }
        float s0 = b0 + sum2(s02);
        float s1 = b1 + sum2(s12);
        out[(bt0 + r) * NQ + q] = tanh_poly(s0) * a0 + tanh_poly(s1) * a1;
    }
}

extern "C" void kernel_launch(void* const* d_in, const int* in_sizes, int n_in,
                              void* d_out, int out_size) {
    const float* f    = (const float*)d_in[0];
    const float* p    = (const float*)d_in[1];
    const float* sp   = (const float*)d_in[2];
    const float* ep   = (const float*)d_in[3];
    const float* emb  = (const float*)d_in[4];
    const float* wiha = (const float*)d_in[5];
    const float* whha = (const float*)d_in[6];
    const float* wihb = (const float*)d_in[7];
    const float* whhb = (const float*)d_in[8];
    const float* a    = (const float*)d_in[9];
    const float* fcw  = (const float*)d_in[10];
    const float* fcb  = (const float*)d_in[11];
    float* out = (float*)d_out;

    k_nop<<<1, 32>>>();   // keeps k_scanA in ncu's 4th-launch capture slot
    {
        dim3 g(GA / 64, NQ / 32, 3);
        k_proj<<<g, 256>>>(emb, wiha);
    }
    {
        dim3 g(GA / 64, (NB * NT) / 64, 1);
        k_gia<<<g, 256>>>(f, p, sp, ep, wiha);
    }
    k_scanA<<<(NB / 2) * 4, GA>>>(whha);
    k_gib<<<(NB * NT) / 64, 384>>>(f, wihb);
    k_scanB<<<NB / 4, 128>>>(whhb);
    k_fc<<<(NB * NT) / 32, 256>>>(fcw, fcb, a, out);
}

// round 17
// speedup vs baseline: 1.2920x; 1.2920x over previous
#include <cuda_runtime.h>
#include <math.h>

#define NB 32
#define NT 2048
#define CF 128
#define NQ 256
#define HA 192
#define GA 576
#define HB 32
#define GB 96
#define JC 48

typedef unsigned long long ull;

__device__ float  g_embA[3 * NQ * GA];
__device__ float  g_gia[NB * NT * GA];
__device__ float  g_ha [NB * NT * HA];
__device__ float  g_gib[NB * NT * GB];
__device__ float  g_hb [NB * NT * HB];

__device__ __forceinline__ float sigf(float x) { return 1.f / (1.f + __expf(-x)); }
__device__ __forceinline__ float tanh_fast(float x) {
    float t = __expf(-2.f * fabsf(x));
    return copysignf(__fdividef(1.f - t, 1.f + t), x);
}
__device__ __forceinline__ float tanh_poly(float x) {
    float t = __expf(-2.f * fabsf(x));
    float u = 1.f + t;
    float d = fmaf(-0.5f, t, 1.f);
    d = d * fmaf(-u, d, 2.f);
    d = d * fmaf(-u, d, 2.f);
    d = d * fmaf(-u, d, 2.f);
    return copysignf((1.f - t) * d, x);
}
__device__ __forceinline__ ull fma2(ull a, ull b, ull c) {
    ull d;
    asm("fma.rn.f32x2 %0, %1, %2, %3;" : "=l"(d) : "l"(a), "l"(b), "l"(c));
    return d;
}
__device__ __forceinline__ float sum2(ull a) {
    float lo, hi;
    asm("mov.b64 {%0,%1}, %2;" : "=f"(lo), "=f"(hi) : "l"(a));
    return lo + hi;
}
__device__ __forceinline__ ull splat2(float x) {
    ull d;
    asm("mov.b64 %0, {%1, %1};" : "=l"(d) : "f"(x));
    return d;
}
__device__ __forceinline__ float2 unpk2(ull a) {
    float lo, hi;
    asm("mov.b64 {%0,%1}, %2;" : "=f"(lo), "=f"(hi) : "l"(a));
    return make_float2(lo, hi);
}
__device__ __forceinline__ unsigned smem_u32(const void* p) {
    unsigned a;
    asm("{ .reg .u64 t; cvta.to.shared.u64 t, %1; cvt.u32.u64 %0, t; }" : "=r"(a) : "l"(p));
    return a;
}
__device__ __forceinline__ unsigned mapa_u32(unsigned a, unsigned rank) {
    unsigned r;
    asm("mapa.shared::cluster.u32 %0, %1, %2;" : "=r"(r) : "r"(a), "r"(rank));
    return r;
}

// K-nop: keeps k_scanA in the ncu-captured 4th-launch slot.
__global__ void k_nop() {}

// K1: embA[s][q][o] = sum_d emb[q][d] * w_ih_a[o][128 + s*256 + d]
__global__ void k_proj(const float* __restrict__ emb, const float* __restrict__ wiha) {
    __shared__ float es[32][65];
    __shared__ float ws[64][65];
    int s = blockIdx.z, q0 = blockIdx.y * 32, o0 = blockIdx.x * 64;
    int t = threadIdx.x, tx = t % 64, ty = t / 64;
    float acc[8];
#pragma unroll
    for (int m = 0; m < 8; m++) acc[m] = 0.f;
    for (int kc = 0; kc < 4; kc++) {
        int k0 = kc * 64;
        for (int i = t; i < 32 * 64; i += 256) {
            int r = i >> 6, c = i & 63;
            es[r][c] = emb[(q0 + r) * NQ + k0 + c];
        }
        for (int i = t; i < 64 * 64; i += 256) {
            int r = i >> 6, c = i & 63;
            ws[r][c] = wiha[(o0 + r) * 896 + 128 + s * 256 + k0 + c];
        }
        __syncthreads();
#pragma unroll 8
        for (int k = 0; k < 64; k++) {
            float wv = ws[tx][k];
#pragma unroll
            for (int m = 0; m < 8; m++) acc[m] = fmaf(es[ty + 4 * m][k], wv, acc[m]);
        }
        __syncthreads();
    }
#pragma unroll
    for (int m = 0; m < 8; m++)
        g_embA[(s * NQ + q0 + ty + 4 * m) * GA + o0 + tx] = acc[m];
}

// K2: gia = f @ Wf^T + lerp(embA). k-major conflict-free tiles + FFMA2 compute.
__global__ void k_gia(const float* __restrict__ f, const float* __restrict__ p,
                      const float* __restrict__ sp, const float* __restrict__ ep,
                      const float* __restrict__ wiha) {
    __shared__ float fsk[64][68];
    __shared__ float wsk[64][68];
    __shared__ int   slo[3][64];
    __shared__ float sfr[3][64];
    int o0 = blockIdx.x * 64, bt0 = blockIdx.y * 64;
    int t = threadIdx.x, tx = t & 15, ty = t >> 4;
    if (t < 192) {
        int c = t >> 6, r = t & 63;
        const float* src = (c == 0) ? p : ((c == 1) ? sp : ep);
        float raw = src[bt0 + r] * 255.f;
        int lo = (int)floorf(raw);
        lo = max(0, min(lo, 254));
        slo[c][r] = lo;
        sfr[c][r] = raw - (float)lo;
    }
    ull acc2[4][2];
#pragma unroll
    for (int i = 0; i < 4; i++) { acc2[i][0] = 0ull; acc2[i][1] = 0ull; }
    for (int kc = 0; kc < 2; kc++) {
        int k0 = kc * 64;
        for (int i = t; i < 64 * 64; i += 256) {
            int r = i >> 6, c = i & 63;
            fsk[c][r] = f[(bt0 + r) * CF + k0 + c];
        }
        for (int i = t; i < 64 * 64; i += 256) {
            int r = i >> 6, c = i & 63;
            wsk[c][r] = wiha[(o0 + r) * 896 + k0 + c];
        }
        __syncthreads();
#pragma unroll 4
        for (int k = 0; k < 64; k++) {
            ulonglong2 wv2 = *(const ulonglong2*)&wsk[k][4 * tx];
            float4 fv = *(const float4*)&fsk[k][4 * ty];
            ull f0 = splat2(fv.x), f1 = splat2(fv.y), f2 = splat2(fv.z), f3 = splat2(fv.w);
            acc2[0][0] = fma2(f0, wv2.x, acc2[0][0]);
            acc2[0][1] = fma2(f0, wv2.y, acc2[0][1]);
            acc2[1][0] = fma2(f1, wv2.x, acc2[1][0]);
            acc2[1][1] = fma2(f1, wv2.y, acc2[1][1]);
            acc2[2][0] = fma2(f2, wv2.x, acc2[2][0]);
            acc2[2][1] = fma2(f2, wv2.y, acc2[2][1]);
            acc2[3][0] = fma2(f3, wv2.x, acc2[3][0]);
            acc2[3][1] = fma2(f3, wv2.y, acc2[3][1]);
        }
        __syncthreads();
    }
#pragma unroll
    for (int i = 0; i < 4; i++) {
        int r = 4 * ty + i;
        float2 p01 = unpk2(acc2[i][0]);
        float2 p23 = unpk2(acc2[i][1]);
        float a0v = p01.x, a1v = p01.y, a2v = p23.x, a3v = p23.y;
#pragma unroll
        for (int c = 0; c < 3; c++) {
            int   lo = slo[c][r];
            float fr = sfr[c][r];
            const float4 v0 = *(const float4*)&g_embA[(c * NQ + lo) * GA + o0 + 4 * tx];
            const float4 v1 = *(const float4*)&g_embA[(c * NQ + lo + 1) * GA + o0 + 4 * tx];
            a0v += v0.x + fr * (v1.x - v0.x);
            a1v += v0.y + fr * (v1.y - v0.y);
            a2v += v0.z + fr * (v1.z - v0.z);
            a3v += v0.w + fr * (v1.w - v0.w);
        }
        *(float4*)&g_gia[(bt0 + r) * GA + o0 + 4 * tx] = make_float4(a0v, a1v, a2v, a3v);
    }
}

// K3: GRU-A scan — R12 topology (1 batch / 4-CTA cluster, owner-directed
// exchange) with the cluster barrier replaced by a transaction-counting
// mbarrier: remote partials via st.async complete_tx (sent in FMA phase,
// latency overlapped), owners try_wait (~90cyc) instead of barrier (~490).
__global__ void __cluster_dims__(4, 1, 1) __launch_bounds__(GA, 1)
k_scanA(const float* __restrict__ whha) {
    __shared__ __align__(16) float hbuf[2][JC];
    __shared__ float part[2][4][GA];
    __shared__ __align__(8) ull mbar[2];

    int o = threadIdx.x;
    int cid = blockIdx.x >> 2;
    unsigned rank;
    asm("mov.u32 %0, %%cluster_ctarank;" : "=r"(rank));

    ull w2[24];
    {
        const ulonglong2* wp = (const ulonglong2*)(whha + o * HA + rank * JC);
#pragma unroll
        for (int k = 0; k < 12; k++) {
            ulonglong2 v = wp[k];
            w2[2 * k] = v.x;
            w2[2 * k + 1] = v.y;
        }
    }

    if (o < JC) hbuf[0][o] = 0.f;
    if (o == 0) {
        asm volatile("mbarrier.init.shared.b64 [%0], 1;" :: "r"(smem_u32(&mbar[0])) : "memory");
        asm volatile("mbarrier.init.shared.b64 [%0], 1;" :: "r"(smem_u32(&mbar[1])) : "memory");
    }
    __syncthreads();
    asm volatile("barrier.cluster.arrive.aligned;" ::: "memory");
    asm volatile("barrier.cluster.wait.aligned;" ::: "memory");

    int owner = (o % HA) / JC;
    bool local_dst = (owner == (int)rank);
    unsigned pa[2], pm[2];
#pragma unroll
    for (int b = 0; b < 2; b++) {
        pa[b] = mapa_u32(smem_u32(&part[b][rank][o]), (unsigned)owner);
        pm[b] = mapa_u32(smem_u32(&mbar[b]), (unsigned)owner);
    }
    unsigned mb_loc[2] = { smem_u32(&mbar[0]), smem_u32(&mbar[1]) };

    const float* gia = g_gia + (size_t)cid * NT * GA;
    bool gate = (o < HA) && (o / JC == (int)rank);
    float h_old = 0.f;
    float gr_i = 0.f, gz_i = 0.f, gn_i = 0.f;
    if (gate) {
        gr_i = gia[o]; gz_i = gia[HA + o]; gn_i = gia[2 * HA + o];
    }

    for (int t = 0; t < NT; t++) {
        int b = t & 1;
        float ngr = 0.f, ngz = 0.f, ngn = 0.f;
        if (gate && t + 1 < NT) {
            const float* g2 = gia + (size_t)(t + 1) * GA;
            ngr = g2[o]; ngz = g2[HA + o]; ngn = g2[2 * HA + o];
        }
        // expect 3 peers x 144 floats = 1728 bytes of remote partials this step
        if (o == 0)
            asm volatile("mbarrier.arrive.expect_tx.shared.b64 _, [%0], %1;"
                         :: "r"(mb_loc[b]), "r"(1728u) : "memory");

        ull a0 = 0ull, a1 = 0ull, a2 = 0ull, a3 = 0ull;
        const ulonglong2* h2 = (const ulonglong2*)hbuf[b];
#pragma unroll
        for (int k = 0; k < 6; k++) {
            ulonglong2 hv0 = h2[2 * k];
            ulonglong2 hv1 = h2[2 * k + 1];
            a0 = fma2(w2[4 * k + 0], hv0.x, a0);
            a1 = fma2(w2[4 * k + 1], hv0.y, a1);
            a2 = fma2(w2[4 * k + 2], hv1.x, a2);
            a3 = fma2(w2[4 * k + 3], hv1.y, a3);
        }
        float ps = (sum2(a0) + sum2(a1)) + (sum2(a2) + sum2(a3));
        if (local_dst)
            part[b][rank][o] = ps;
        else
            asm volatile("st.async.shared::cluster.mbarrier::complete_tx::bytes.f32 [%0], %1, [%2];"
                         :: "r"(pa[b]), "f"(ps), "r"(pm[b]) : "memory");

        __syncthreads();   // local partials visible; all sends issued

        if (gate) {
            // wait for remote partials (tx-counting mbarrier, double buffered)
            unsigned par = (t >> 1) & 1;
            asm volatile(
                "{\n\t.reg .pred P;\n\t"
                "W_%=:\n\t"
                "mbarrier.try_wait.parity.acquire.cluster.shared::cta.b64 P, [%0], %1, 0x989680;\n\t"
                "@P bra D_%=;\n\t"
                "bra W_%=;\n\t"
                "D_%=:\n\t}"
                :: "r"(mb_loc[b]), "r"(par) : "memory");

            float rr = gr_i, zz = gz_i, np = 0.f;
#pragma unroll
            for (int k = 0; k < 4; k++) {
                rr += part[b][k][o];
                zz += part[b][k][HA + o];
                np += part[b][k][2 * HA + o];
            }
            float rg = sigf(rr);
            float zg = sigf(zz);
            float n  = tanh_fast(gn_i + rg * np);
            float hn = (1.f - zg) * n + zg * h_old;
            h_old = hn;
            hbuf[b ^ 1][o - (int)rank * JC] = hn;
            g_ha[(size_t)(cid * NT + t) * HA + o] = hn;
        }
        __syncthreads();
        gr_i = ngr; gz_i = ngz; gn_i = ngn;
    }
    asm volatile("barrier.cluster.arrive.aligned;" ::: "memory");
    asm volatile("barrier.cluster.wait.aligned;" ::: "memory");
}

// K4: gib = concat(h_a, f) @ w_ih_b^T. k-major tiles + FFMA2 compute.
__global__ void __launch_bounds__(384) k_gib(const float* __restrict__ f,
                                             const float* __restrict__ wihb) {
    __shared__ float xsk[64][68];
    __shared__ float wskb[64][100];
    int bt0 = blockIdx.x * 64;
    int t = threadIdx.x, tx = t % 24, ty = t / 24;
    ull acc2[4][2];
#pragma unroll
    for (int i = 0; i < 4; i++) { acc2[i][0] = 0ull; acc2[i][1] = 0ull; }
    for (int kc = 0; kc < 5; kc++) {
        int k0 = kc * 64;
        for (int i = t; i < 64 * 64; i += 384) {
            int r = i >> 6, c = i & 63;
            xsk[c][r] = (k0 < HA) ? g_ha[(bt0 + r) * HA + k0 + c]
                                  : f[(bt0 + r) * CF + (k0 - HA) + c];
        }
        for (int i = t; i < 96 * 64; i += 384) {
            int r = i >> 6, c = i & 63;
            wskb[c][r] = wihb[r * 320 + k0 + c];
        }
        __syncthreads();
#pragma unroll 4
        for (int k = 0; k < 64; k++) {
            ulonglong2 wv2 = *(const ulonglong2*)&wskb[k][4 * tx];
            float4 xv = *(const float4*)&xsk[k][4 * ty];
            ull x0 = splat2(xv.x), x1 = splat2(xv.y), x2 = splat2(xv.z), x3 = splat2(xv.w);
            acc2[0][0] = fma2(x0, wv2.x, acc2[0][0]);
            acc2[0][1] = fma2(x0, wv2.y, acc2[0][1]);
            acc2[1][0] = fma2(x1, wv2.x, acc2[1][0]);
            acc2[1][1] = fma2(x1, wv2.y, acc2[1][1]);
            acc2[2][0] = fma2(x2, wv2.x, acc2[2][0]);
            acc2[2][1] = fma2(x2, wv2.y, acc2[2][1]);
            acc2[3][0] = fma2(x3, wv2.x, acc2[3][0]);
            acc2[3][1] = fma2(x3, wv2.y, acc2[3][1]);
        }
        __syncthreads();
    }
#pragma unroll
    for (int i = 0; i < 4; i++) {
        float2 p01 = unpk2(acc2[i][0]);
        float2 p23 = unpk2(acc2[i][1]);
        *(float4*)&g_gib[(bt0 + 4 * ty + i) * GB + 4 * tx] =
            make_float4(p01.x, p01.y, p23.x, p23.y);
    }
}

// K5: GRU-B scan — 4 batches/CTA, one warp per batch, h in smem, FFMA2
__global__ void __launch_bounds__(128) k_scanB(const float* __restrict__ whhb) {
    __shared__ __align__(16) float hsm[4][HB];
    int l = threadIdx.x & 31, wi = threadIdx.x >> 5;
    int b = blockIdx.x * 4 + wi;
    ull wr2[16], wz2[16], wn2[16];
    {
        const ulonglong2* pr = (const ulonglong2*)(whhb + l * HB);
        const ulonglong2* pz = (const ulonglong2*)(whhb + (HB + l) * HB);
        const ulonglong2* pn = (const ulonglong2*)(whhb + (2 * HB + l) * HB);
#pragma unroll
        for (int k = 0; k < 8; k++) {
            ulonglong2 vr = pr[k], vz = pz[k], vn = pn[k];
            wr2[2 * k] = vr.x; wr2[2 * k + 1] = vr.y;
            wz2[2 * k] = vz.x; wz2[2 * k + 1] = vz.y;
            wn2[2 * k] = vn.x; wn2[2 * k + 1] = vn.y;
        }
    }
    float h = 0.f;
    hsm[wi][l] = 0.f;
    __syncwarp();
    int bT = b * NT;
    const float* gi0 = &g_gib[(size_t)bT * GB];
    float gi_r = gi0[l], gi_z = gi0[HB + l], gi_n = gi0[2 * HB + l];
    for (int t = 0; t < NT; t++) {
        float nr = 0.f, nz = 0.f, nn = 0.f;
        if (t + 1 < NT) {
            const float* g2 = &g_gib[(size_t)(bT + t + 1) * GB];
            nr = g2[l]; nz = g2[HB + l]; nn = g2[2 * HB + l];
        }
        ull ar = 0ull, az = 0ull, an = 0ull;
        const ulonglong2* h2 = (const ulonglong2*)hsm[wi];
#pragma unroll
        for (int k = 0; k < 8; k++) {
            ulonglong2 hv = h2[k];
            ar = fma2(wr2[2 * k], hv.x, ar);
            az = fma2(wz2[2 * k], hv.x, az);
            an = fma2(wn2[2 * k], hv.x, an);
            ar = fma2(wr2[2 * k + 1], hv.y, ar);
            az = fma2(wz2[2 * k + 1], hv.y, az);
            an = fma2(wn2[2 * k + 1], hv.y, an);
        }
        float r = sigf(gi_r + sum2(ar));
        float z = sigf(gi_z + sum2(az));
        float n = tanh_fast(gi_n + r * sum2(an));
        h = (1.f - z) * n + z * h;
        __syncwarp();
        hsm[wi][l] = h;
        g_hb[(size_t)(bT + t) * HB + l] = h;
        __syncwarp();
        gi_r = nr; gi_z = nz; gi_n = nn;
    }
}

// K6: out[bt][q] = tanh(fc)*a summed over pair — FFMA2 dot products.
__global__ void __launch_bounds__(256) k_fc(const float* __restrict__ fcw,
                                            const float* __restrict__ fcb,
                                            const float* __restrict__ a,
                                            float* __restrict__ out) {
    __shared__ __align__(8) float hs[32][34];
    int q = threadIdx.x;
    int bt0 = blockIdx.x * 32;
    for (int i = q; i < 32 * 32; i += 256) {
        int r = i >> 5, c = i & 31;
        hs[r][c] = g_hb[(bt0 + r) * HB + c];
    }
    __syncthreads();
    ull w02[16], w12[16];
    {
        const ulonglong2* p0 = (const ulonglong2*)(fcw + (2 * q) * HB);
        const ulonglong2* p1 = (const ulonglong2*)(fcw + (2 * q + 1) * HB);
#pragma unroll
        for (int k = 0; k < 8; k++) {
            ulonglong2 v0 = p0[k], v1 = p1[k];
            w02[2 * k] = v0.x; w02[2 * k + 1] = v0.y;
            w12[2 * k] = v1.x; w12[2 * k + 1] = v1.y;
        }
    }
    float b0 = fcb[2 * q], b1 = fcb[2 * q + 1];
    float a0 = a[2 * q],   a1 = a[2 * q + 1];
    for (int r = 0; r < 32; r++) {
        ull s02 = 0ull, s12 = 0ull;
        const ull* hv2 = (const ull*)hs[r];
#pragma unroll
        for (int k = 0; k < 16; k++) {
            ull hv = hv2[k];
            s02 = fma2(w02[k], hv, s02);
            s12 = fma2(w12[k], hv, s12);
        }
        float s0 = b0 + sum2(s02);
        float s1 = b1 + sum2(s12);
        out[(bt0 + r) * NQ + q] = tanh_poly(s0) * a0 + tanh_poly(s1) * a1;
    }
}

extern "C" void kernel_launch(void* const* d_in, const int* in_sizes, int n_in,
                              void* d_out, int out_size) {
    const float* f    = (const float*)d_in[0];
    const float* p    = (const float*)d_in[1];
    const float* sp   = (const float*)d_in[2];
    const float* ep   = (const float*)d_in[3];
    const float* emb  = (const float*)d_in[4];
    const float* wiha = (const float*)d_in[5];
    const float* whha = (const float*)d_in[6];
    const float* wihb = (const float*)d_in[7];
    const float* whhb = (const float*)d_in[8];
    const float* a    = (const float*)d_in[9];
    const float* fcw  = (const float*)d_in[10];
    const float* fcb  = (const float*)d_in[11];
    float* out = (float*)d_out;

    k_nop<<<1, 32>>>();   // keeps k_scanA in ncu's 4th-launch capture slot
    {
        dim3 g(GA / 64, NQ / 32, 3);
        k_proj<<<g, 256>>>(emb, wiha);
    }
    {
        dim3 g(GA / 64, (NB * NT) / 64, 1);
        k_gia<<<g, 256>>>(f, p, sp, ep, wiha);
    }
    k_scanA<<<NB * 4, GA>>>(whha);
    k_gib<<<(NB * NT) / 64, 384>>>(f, wihb);
    k_scanB<<<NB / 4, 128>>>(whhb);
    k_fc<<<(NB * NT) / 32, 256>>>(fcw, fcb, a, out);
}